// round 15
// baseline (speedup 1.0000x reference)
#include <cuda_runtime.h>
#include <stdint.h>
#include <math.h>

// Sizes (fixed for this problem)
#define BB 16
#define LL 128
#define HH 256
#define DD 256
#define BL (BB*LL)              // 2048
#define NEL (BB*LL*LL)          // 262144
#define OFF_MS 0
#define OFF_S  NEL              // 262144
#define OFF_E  (2*NEL)          // 524288
#define OFF_GB (3*NEL)          // 786432
#define OFF_LSM (3*NEL + LL*LL) // 802816
#define OFF_ER (OFF_LSM + 1)    // 802817

// Scratch (no cudaMalloc allowed).
__device__ float g_el[BL*DD];        // exp(2*dot_l)
__device__ float g_er[BL*DD];        // exp(2*dot_r)
__device__ float g_ent_part[512];
__device__ float g_lsm_part[512];
__device__ int   g_cnt[LL*LL];       // zero at load; last block resets
__device__ int   g_done;             // block completion counter

#define TWO_LOG2E 2.8853900817779268f   // 2*log2(e)

__device__ __forceinline__ float ex2f(float x) {
    float e; asm("ex2.approx.f32 %0, %1;" : "=f"(e) : "f"(x)); return e;
}
__device__ __forceinline__ float rcpf(float x) {
    float r; asm("rcp.approx.f32 %0, %1;" : "=f"(r) : "f"(x)); return r;
}

// ---------------------------------------------------------------------------
// 4xTF32 split helpers (fp32-equivalent accuracy on tensor pipe)
// ---------------------------------------------------------------------------
__device__ __forceinline__ void tf32_split(float x, uint32_t& hi, uint32_t& lo) {
    asm("cvt.rna.tf32.f32 %0, %1;" : "=r"(hi) : "f"(x));
    float l = x - __uint_as_float(hi);
    asm("cvt.rna.tf32.f32 %0, %1;" : "=r"(lo) : "f"(l));
}
__device__ __forceinline__ void split4(float4 v, float4& h, float4& l) {
    uint32_t hh, ll;
    tf32_split(v.x, hh, ll); h.x = __uint_as_float(hh); l.x = __uint_as_float(ll);
    tf32_split(v.y, hh, ll); h.y = __uint_as_float(hh); l.y = __uint_as_float(ll);
    tf32_split(v.z, hh, ll); h.z = __uint_as_float(hh); l.z = __uint_as_float(ll);
    tf32_split(v.w, hh, ll); h.w = __uint_as_float(hh); l.w = __uint_as_float(ll);
}
__device__ __forceinline__ void mma_tf32(float* c, const uint32_t* a,
                                         const uint32_t* b) {
    asm volatile(
        "mma.sync.aligned.m16n8k8.row.col.f32.tf32.tf32.f32 "
        "{%0,%1,%2,%3}, {%4,%5,%6,%7}, {%8,%9}, {%0,%1,%2,%3};"
        : "+f"(c[0]), "+f"(c[1]), "+f"(c[2]), "+f"(c[3])
        : "r"(a[0]), "r"(a[1]), "r"(a[2]), "r"(a[3]), "r"(b[0]), "r"(b[1]));
}

// ---------------------------------------------------------------------------
// GEMM (tensor core): C = exp(2 * (A @ W)), TF32 split at STS time.
// 128 tiles of 128m x 64n -> grid (4, 16, 2) = 128 blocks, 1 per SM, 1 wave.
// 256 thr / 8 warps; warp tile 32m x 32n (2 m-frags x 4 n-frags m16n8k8).
// k staged 32/stage, 8 stages. Inner loop pure LDS + MMA. (unchanged)
// ---------------------------------------------------------------------------
#define GA_STR 36
#define GB_STR 72

__global__ __launch_bounds__(256, 1)
void gemm_tc_kernel(const float* __restrict__ A,
                    const float* __restrict__ Wl,
                    const float* __restrict__ Wr) {
    const float* W = blockIdx.z ? Wr : Wl;
    float* C = blockIdx.z ? g_er : g_el;
    __shared__ __align__(16) float Ash[128 * GA_STR];
    __shared__ __align__(16) float Asl[128 * GA_STR];
    __shared__ __align__(16) float Bsh[32 * GB_STR];
    __shared__ __align__(16) float Bsl[32 * GB_STR];
    const int tid = threadIdx.x;
    const int w = tid >> 5, lane = tid & 31;
    const int m0 = blockIdx.y * 128, n0 = blockIdx.x * 64;
    const int wm = (w >> 1) * 32, wn = (w & 1) * 32;
    const int r = lane >> 2, cq = lane & 3;

    int aro[4], aco[4];
#pragma unroll
    for (int q = 0; q < 4; q++) {
        int idx = q * 256 + tid;
        aro[q] = idx >> 3; aco[q] = (idx & 7) * 4;
    }
    int bro[2], bco[2];
#pragma unroll
    for (int q = 0; q < 2; q++) {
        int idx = q * 256 + tid;
        bro[q] = idx >> 4; bco[q] = (idx & 15) * 4;
    }

    float4 ra[4], rb[2];
#pragma unroll
    for (int q = 0; q < 4; q++)
        ra[q] = *(const float4*)&A[(m0 + aro[q]) * 256 + aco[q]];
#pragma unroll
    for (int q = 0; q < 2; q++)
        rb[q] = *(const float4*)&W[bro[q] * 256 + n0 + bco[q]];

    float acc[2][4][4];
#pragma unroll
    for (int mi = 0; mi < 2; mi++)
#pragma unroll
        for (int ni = 0; ni < 4; ni++)
#pragma unroll
            for (int q = 0; q < 4; q++) acc[mi][ni][q] = 0.0f;

    for (int s = 0; s < 8; s++) {
        float4 h, l;
#pragma unroll
        for (int q = 0; q < 4; q++) {
            split4(ra[q], h, l);
            *(float4*)&Ash[aro[q] * GA_STR + aco[q]] = h;
            *(float4*)&Asl[aro[q] * GA_STR + aco[q]] = l;
        }
#pragma unroll
        for (int q = 0; q < 2; q++) {
            split4(rb[q], h, l);
            *(float4*)&Bsh[bro[q] * GB_STR + bco[q]] = h;
            *(float4*)&Bsl[bro[q] * GB_STR + bco[q]] = l;
        }
        __syncthreads();
        if (s < 7) {
#pragma unroll
            for (int q = 0; q < 4; q++)
                ra[q] = *(const float4*)&A[(m0 + aro[q]) * 256 + (s + 1) * 32 + aco[q]];
#pragma unroll
            for (int q = 0; q < 2; q++)
                rb[q] = *(const float4*)&W[((s + 1) * 32 + bro[q]) * 256 + n0 + bco[q]];
        }
#pragma unroll
        for (int k8 = 0; k8 < 32; k8 += 8) {
            uint32_t ahi[2][4], alo[2][4];
#pragma unroll
            for (int mi = 0; mi < 2; mi++) {
                const int base = (wm + mi * 16 + r) * GA_STR + k8 + cq;
                ahi[mi][0] = __float_as_uint(Ash[base]);
                ahi[mi][1] = __float_as_uint(Ash[base + 8 * GA_STR]);
                ahi[mi][2] = __float_as_uint(Ash[base + 4]);
                ahi[mi][3] = __float_as_uint(Ash[base + 8 * GA_STR + 4]);
                alo[mi][0] = __float_as_uint(Asl[base]);
                alo[mi][1] = __float_as_uint(Asl[base + 8 * GA_STR]);
                alo[mi][2] = __float_as_uint(Asl[base + 4]);
                alo[mi][3] = __float_as_uint(Asl[base + 8 * GA_STR + 4]);
            }
            uint32_t bhi[4][2], blo[4][2];
#pragma unroll
            for (int ni = 0; ni < 4; ni++) {
                const int base = (k8 + cq) * GB_STR + wn + ni * 8 + r;
                bhi[ni][0] = __float_as_uint(Bsh[base]);
                bhi[ni][1] = __float_as_uint(Bsh[base + 4 * GB_STR]);
                blo[ni][0] = __float_as_uint(Bsl[base]);
                blo[ni][1] = __float_as_uint(Bsl[base + 4 * GB_STR]);
            }
#pragma unroll
            for (int mi = 0; mi < 2; mi++)
#pragma unroll
                for (int ni = 0; ni < 4; ni++) {
                    mma_tf32(acc[mi][ni], alo[mi], blo[ni]);
                    mma_tf32(acc[mi][ni], alo[mi], bhi[ni]);
                    mma_tf32(acc[mi][ni], ahi[mi], blo[ni]);
                    mma_tf32(acc[mi][ni], ahi[mi], bhi[ni]);
                }
        }
        __syncthreads();
    }

#pragma unroll
    for (int mi = 0; mi < 2; mi++)
#pragma unroll
        for (int ni = 0; ni < 4; ni++) {
            int row = m0 + wm + mi * 16 + r;
            int col = n0 + wn + ni * 8 + 2 * cq;
            float2 lo2, hi2;
            lo2.x = ex2f(acc[mi][ni][0] * TWO_LOG2E);
            lo2.y = ex2f(acc[mi][ni][1] * TWO_LOG2E);
            hi2.x = ex2f(acc[mi][ni][2] * TWO_LOG2E);
            hi2.y = ex2f(acc[mi][ni][3] * TWO_LOG2E);
            *(float2*)&C[row * 256 + col]       = lo2;
            *(float2*)&C[(row + 8) * 256 + col] = hi2;
        }
}

// ---------------------------------------------------------------------------
// Threefry-2x32, key = (0,1) [jax.random.key(1)], partitionable bits.
// ---------------------------------------------------------------------------
__device__ __forceinline__ uint32_t rotl32(uint32_t v, int r) {
    return __funnelshift_l(v, v, r);
}
__device__ __forceinline__ uint32_t threefry_bits(uint32_t idx) {
    const uint32_t K0 = 0u, K1 = 1u, K2 = 0x1BD11BDBu;
    uint32_t x0 = K0;
    uint32_t x1 = idx + K1;
#define TF_ROUND(r) { x0 += x1; x1 = rotl32(x1, (r)); x1 ^= x0; }
    TF_ROUND(13) TF_ROUND(15) TF_ROUND(26) TF_ROUND(6)
    x0 += K1; x1 += K2 + 1u;
    TF_ROUND(17) TF_ROUND(29) TF_ROUND(16) TF_ROUND(24)
    x0 += K2; x1 += K0 + 2u;
    TF_ROUND(13) TF_ROUND(15) TF_ROUND(26) TF_ROUND(6)
    x0 += K0; x1 += K1 + 3u;
    TF_ROUND(17) TF_ROUND(29) TF_ROUND(16) TF_ROUND(24)
    x0 += K1; x1 += K2 + 4u;
    TF_ROUND(13) TF_ROUND(15) TF_ROUND(26) TF_ROUND(6)
    x0 += K2; x1 += K0 + 5u;
#undef TF_ROUND
    return x0 ^ x1;
}

// Epilogue for one (b,i,j): writes ms/sample/entropy, counts sample into
// g_cnt (integer atomic -> deterministic), returns (entropy, lsm_term).
__device__ __forceinline__ float2 epi_one(int b, int i, int j, float logit,
                                          float* __restrict__ out) {
    float ms = (i == j) ? (logit - 1e8f) : logit;
    uint32_t f = ((uint32_t)b << 14) | ((uint32_t)i << 7) | (uint32_t)j;
    uint32_t bits = threefry_bits(f);
    float u = __uint_as_float((bits >> 9) | 0x3f800000u) - 1.0f;
    float p = 1.0f / (1.0f + expf(-ms));
    float c = log1pf(expf(-fabsf(ms)));          // shared softplus tail
    float sp_pos = fmaxf(ms, 0.0f) + c;          // softplus(ms)
    float sp_neg = fmaxf(-ms, 0.0f) + c;         // softplus(-ms)
    float ent = fmaf(p, sp_neg, (1.0f - p) * sp_pos);
    float s;
    if (u < p) { s = 1.0f; atomicAdd(&g_cnt[i * LL + j], 1); } else s = 0.0f;
    out[OFF_MS + f] = ms;
    out[OFF_S + f]  = s;
    out[OFF_E + f]  = ent;
    float lsm = sp_pos - ms * s;
    return make_float2(ent, lsm);
}

// ---------------------------------------------------------------------------
// Pairwise core — EXACT R6 shape (proven ~26us) + fused tail.
// grid (8, 4, 16): x = j-tile(16), y = i-tile(32), z = batch; 256 threads
// (ty = i 0..31 = tid>>3, tx = j 0..7 = tid&7; each thread does j and j+8).
// Full D=256 in smem (sl 32 rows, sr 16 rows, stride 260). 512 blocks.
// ---------------------------------------------------------------------------
#define PW_STR 260

__global__ __launch_bounds__(256, 4)
void pairwise_kernel(const float* __restrict__ Uv,
                     const float* __restrict__ biasp,
                     float* __restrict__ out) {
    __shared__ __align__(16) float sl[32 * PW_STR];
    __shared__ __align__(16) float sr[16 * PW_STR];
    __shared__ __align__(16) float su[256];
    __shared__ float rshare[2][8];
    __shared__ int s_last;
    const int tid = threadIdx.x;
    const int tx = tid & 7, ty = tid >> 3;        // j, i within tile
    const int b = blockIdx.z;
    const int ibase = blockIdx.y * 32, jbase = blockIdx.x * 16;

    su[tid] = Uv[tid];
    // load 32 l-rows + 16 r-rows, each 256 floats (64 float4), coalesced
    for (int idx = tid; idx < 48 * 64; idx += 256) {
        int r = idx >> 6, c = (idx & 63) * 4;
        if (r < 32) {
            *(float4*)&sl[r * PW_STR + c] =
                *(const float4*)&g_el[(b * 128 + ibase + r) * 256 + c];
        } else {
            *(float4*)&sr[(r - 32) * PW_STR + c] =
                *(const float4*)&g_er[(b * 128 + jbase + (r - 32)) * 256 + c];
        }
    }
    __syncthreads();

    const float* pl  = sl + ty * PW_STR;
    const float* pr0 = sr + tx * PW_STR;
    const float* pr1 = sr + (tx + 8) * PW_STR;
    float a0 = 0.0f, a1 = 0.0f;
#pragma unroll 4
    for (int d = 0; d < 256; d += 4) {
        float4 L  = *(const float4*)(pl + d);
        float4 R0 = *(const float4*)(pr0 + d);
        float4 R1 = *(const float4*)(pr1 + d);
        float4 UD = *(const float4*)(su + d);
        a0 = fmaf(UD.x, rcpf(fmaf(L.x, R0.x, 1.0f)) - 0.5f, a0);
        a1 = fmaf(UD.x, rcpf(fmaf(L.x, R1.x, 1.0f)) - 0.5f, a1);
        a0 = fmaf(UD.y, rcpf(fmaf(L.y, R0.y, 1.0f)) - 0.5f, a0);
        a1 = fmaf(UD.y, rcpf(fmaf(L.y, R1.y, 1.0f)) - 0.5f, a1);
        a0 = fmaf(UD.z, rcpf(fmaf(L.z, R0.z, 1.0f)) - 0.5f, a0);
        a1 = fmaf(UD.z, rcpf(fmaf(L.z, R1.z, 1.0f)) - 0.5f, a1);
        a0 = fmaf(UD.w, rcpf(fmaf(L.w, R0.w, 1.0f)) - 0.5f, a0);
        a1 = fmaf(UD.w, rcpf(fmaf(L.w, R1.w, 1.0f)) - 0.5f, a1);
    }

    const float bias = __ldg(biasp);
    float2 e0 = epi_one(b, ibase + ty, jbase + tx,     fmaf(-2.0f, a0, bias), out);
    float2 e1 = epi_one(b, ibase + ty, jbase + tx + 8, fmaf(-2.0f, a1, bias), out);

    // block reduce (shfl tree + 8-warp combine), deterministic
    float ent = e0.x + e1.x, lsm = e0.y + e1.y;
#pragma unroll
    for (int o = 16; o > 0; o >>= 1) {
        ent += __shfl_xor_sync(0xffffffffu, ent, o);
        lsm += __shfl_xor_sync(0xffffffffu, lsm, o);
    }
    const int wid = tid >> 5;
    if ((tid & 31) == 0) { rshare[0][wid] = ent; rshare[1][wid] = lsm; }
    __syncthreads();
    if (tid == 0) {
        float se = 0.0f, sm = 0.0f;
#pragma unroll
        for (int w = 0; w < 8; w++) { se += rshare[0][w]; sm += rshare[1][w]; }
        const int bid = (b * 4 + blockIdx.y) * 8 + blockIdx.x; // 0..511
        g_ent_part[bid] = se;
        g_lsm_part[bid] = sm;
    }

    // ---- fused tail: last finishing block ----
    if (tid == 0) {
        __threadfence();
        int d = atomicAdd(&g_done, 1);
        s_last = (d == (int)(gridDim.x * gridDim.y * gridDim.z) - 1) ? 1 : 0;
    }
    __syncthreads();
    if (s_last) {
        __threadfence();
        for (int k = tid; k < LL * LL; k += 256) {
            out[OFF_GB + k] = (float)g_cnt[k] * 0.0625f;
            g_cnt[k] = 0;
        }
        if (tid < 16) {   // entropy_reg: 32 tile-partials per batch, in order
            float s = 0.0f;
#pragma unroll
            for (int k = 0; k < 32; k++) s += g_ent_part[tid * 32 + k];
            out[OFF_ER + tid] = s * (1.0f / 16384.0f);
        }
        if (tid >= 32 && tid < 64) {   // log_softmax: 512 partials
            int ln = tid - 32;
            float s = 0.0f;
#pragma unroll
            for (int k = 0; k < 16; k++) s += g_lsm_part[ln * 16 + k];
#pragma unroll
            for (int o = 16; o > 0; o >>= 1)
                s += __shfl_xor_sync(0xffffffffu, s, o);
            if (ln == 0) out[OFF_LSM] = s * (1.0f / (float)NEL);
        }
        if (tid == 64) g_done = 0;     // reset for graph replay
    }
}

// ---------------------------------------------------------------------------
extern "C" void kernel_launch(void* const* d_in, const int* in_sizes, int n_in,
                              void* d_out, int out_size) {
    (void)in_sizes; (void)n_in; (void)out_size;
    const float* enc  = (const float*)d_in[0]; // (16,128,256)
    const float* W_l  = (const float*)d_in[1]; // (256,256)
    const float* W_r  = (const float*)d_in[2]; // (256,256)
    const float* U    = (const float*)d_in[3]; // (256,)
    const float* bias = (const float*)d_in[4]; // (1,)
    float* out = (float*)d_out;

    gemm_tc_kernel<<<dim3(4, 16, 2), 256>>>(enc, W_l, W_r);
    pairwise_kernel<<<dim3(8, 4, 16), 256>>>(U, bias, out);
}

// round 16
// speedup vs baseline: 1.7639x; 1.7639x over previous
#include <cuda_runtime.h>
#include <stdint.h>
#include <math.h>

// Sizes (fixed for this problem)
#define BB 16
#define LL 128
#define HH 256
#define DD 256
#define BL (BB*LL)              // 2048
#define NEL (BB*LL*LL)          // 262144
#define OFF_MS 0
#define OFF_S  NEL              // 262144
#define OFF_E  (2*NEL)          // 524288
#define OFF_GB (3*NEL)          // 786432
#define OFF_LSM (3*NEL + LL*LL) // 802816
#define OFF_ER (OFF_LSM + 1)    // 802817

// Scratch (no cudaMalloc allowed). g_el/g_er hold exp(2*dot).
__device__ float g_el[BL*DD];
__device__ float g_er[BL*DD];
__device__ float g_ent_part[512];
__device__ float g_lsm_part[512];
__device__ int   g_cnt[LL*LL];   // zero at load; tail kernel resets each call

#define TWO_LOG2E 2.8853900817779268f   // 2*log2(e)

__device__ __forceinline__ float ex2f(float x) {
    float e; asm("ex2.approx.f32 %0, %1;" : "=f"(e) : "f"(x)); return e;
}
__device__ __forceinline__ float rcpf(float x) {
    float r; asm("rcp.approx.f32 %0, %1;" : "=f"(r) : "f"(x)); return r;
}

// ---------------------------------------------------------------------------
// GEMM: C = exp(2 * (A(2048x256) @ W(256x256))), fp32.  (EXACT R8 version)
// 64x64 tile, 128 threads, 8x4 microtile, k-chunk 16, register prefetch.
// As[m][k] stride 20 (LDS.128 a-frags along k), Bs[k][n] stride 68
// (LDS.128 b-frags along n). grid (4, 32, 2) = 256 blocks.
// ---------------------------------------------------------------------------
#define AS_STR 20
#define BS_STR 68

__global__ __launch_bounds__(128, 2)
void gemm_exp_kernel(const float* __restrict__ A,
                     const float* __restrict__ Wl,
                     const float* __restrict__ Wr) {
    const float* W = blockIdx.z ? Wr : Wl;
    float* C = blockIdx.z ? g_er : g_el;
    __shared__ __align__(16) float As[64 * AS_STR];
    __shared__ __align__(16) float Bs[16 * BS_STR];
    const int tid = threadIdx.x;
    const int tx = tid & 15, ty = tid >> 4;       // tx: n (0..15), ty: m (0..7)
    const int m0 = blockIdx.y * 64, n0 = blockIdx.x * 64;

    // global load mapping
    const int arow = tid >> 2, acol = (tid & 3) * 4;   // A: 64 rows x 16 k
    const int brow = tid >> 3, bcol = (tid & 7) * 8;   // W: 16 rows x 64 n
    const float* Ap = A + (m0 + arow) * 256 + acol;
    const float* Wp = W + brow * 256 + n0 + bcol;

    float4 ra0 = *(const float4*)(Ap);
    float4 ra1 = *(const float4*)(Ap + 32 * 256);
    float4 rb0 = *(const float4*)(Wp);
    float4 rb1 = *(const float4*)(Wp + 4);

    float acc[8][4];
#pragma unroll
    for (int u = 0; u < 8; u++)
#pragma unroll
        for (int v = 0; v < 4; v++) acc[u][v] = 0.0f;

    for (int s = 0; s < 16; s++) {
        *(float4*)&As[arow * AS_STR + acol]        = ra0;
        *(float4*)&As[(arow + 32) * AS_STR + acol] = ra1;
        *(float4*)&Bs[brow * BS_STR + bcol]        = rb0;
        *(float4*)&Bs[brow * BS_STR + bcol + 4]    = rb1;
        __syncthreads();
        if (s < 15) {
            ra0 = *(const float4*)(Ap + (s + 1) * 16);
            ra1 = *(const float4*)(Ap + (s + 1) * 16 + 32 * 256);
            rb0 = *(const float4*)(Wp + (s + 1) * 16 * 256);
            rb1 = *(const float4*)(Wp + (s + 1) * 16 * 256 + 4);
        }
#pragma unroll
        for (int kq = 0; kq < 16; kq += 4) {
            // a-fragments: 8 float4 loads, transposed into scalar regs [kk][mi]
            float a_s[4][8];
#pragma unroll
            for (int i = 0; i < 4; i++) {
                float4 lo = *(const float4*)&As[(4 * ty + i) * AS_STR + kq];
                float4 hi = *(const float4*)&As[(32 + 4 * ty + i) * AS_STR + kq];
                a_s[0][i] = lo.x; a_s[1][i] = lo.y; a_s[2][i] = lo.z; a_s[3][i] = lo.w;
                a_s[0][i + 4] = hi.x; a_s[1][i + 4] = hi.y;
                a_s[2][i + 4] = hi.z; a_s[3][i + 4] = hi.w;
            }
            // b-fragments: 4 float4 loads [kk]
            float4 b4[4];
#pragma unroll
            for (int kk = 0; kk < 4; kk++)
                b4[kk] = *(const float4*)&Bs[(kq + kk) * BS_STR + 4 * tx];
#pragma unroll
            for (int kk = 0; kk < 4; kk++) {
#pragma unroll
                for (int mi = 0; mi < 8; mi++) {
                    float av = a_s[kk][mi];
                    acc[mi][0] = fmaf(av, b4[kk].x, acc[mi][0]);
                    acc[mi][1] = fmaf(av, b4[kk].y, acc[mi][1]);
                    acc[mi][2] = fmaf(av, b4[kk].z, acc[mi][2]);
                    acc[mi][3] = fmaf(av, b4[kk].w, acc[mi][3]);
                }
            }
        }
        __syncthreads();
    }
#pragma unroll
    for (int mi = 0; mi < 8; mi++) {
        int m = m0 + ((mi < 4) ? (4 * ty + mi) : (32 + 4 * ty + (mi - 4)));
        float4 o;
        o.x = ex2f(acc[mi][0] * TWO_LOG2E);
        o.y = ex2f(acc[mi][1] * TWO_LOG2E);
        o.z = ex2f(acc[mi][2] * TWO_LOG2E);
        o.w = ex2f(acc[mi][3] * TWO_LOG2E);
        *(float4*)&C[m * 256 + n0 + 4 * tx] = o;
    }
}

// ---------------------------------------------------------------------------
// Threefry-2x32, key = (0,1) [jax.random.key(1)], partitionable bits.
// ---------------------------------------------------------------------------
__device__ __forceinline__ uint32_t rotl32(uint32_t v, int r) {
    return __funnelshift_l(v, v, r);
}
__device__ __forceinline__ uint32_t threefry_bits(uint32_t idx) {
    const uint32_t K0 = 0u, K1 = 1u, K2 = 0x1BD11BDBu;
    uint32_t x0 = K0;
    uint32_t x1 = idx + K1;
#define TF_ROUND(r) { x0 += x1; x1 = rotl32(x1, (r)); x1 ^= x0; }
    TF_ROUND(13) TF_ROUND(15) TF_ROUND(26) TF_ROUND(6)
    x0 += K1; x1 += K2 + 1u;
    TF_ROUND(17) TF_ROUND(29) TF_ROUND(16) TF_ROUND(24)
    x0 += K2; x1 += K0 + 2u;
    TF_ROUND(13) TF_ROUND(15) TF_ROUND(26) TF_ROUND(6)
    x0 += K0; x1 += K1 + 3u;
    TF_ROUND(17) TF_ROUND(29) TF_ROUND(16) TF_ROUND(24)
    x0 += K1; x1 += K2 + 4u;
    TF_ROUND(13) TF_ROUND(15) TF_ROUND(26) TF_ROUND(6)
    x0 += K2; x1 += K0 + 5u;
#undef TF_ROUND
    return x0 ^ x1;
}

// Epilogue for one (b,i,j): writes ms/sample/entropy, counts sample into
// g_cnt (integer atomic -> deterministic), returns (entropy, lsm_term).
__device__ __forceinline__ float2 epi_one(int b, int i, int j, float logit,
                                          float* __restrict__ out) {
    float ms = (i == j) ? (logit - 1e8f) : logit;
    uint32_t f = ((uint32_t)b << 14) | ((uint32_t)i << 7) | (uint32_t)j;
    uint32_t bits = threefry_bits(f);
    float u = __uint_as_float((bits >> 9) | 0x3f800000u) - 1.0f;
    float p = 1.0f / (1.0f + expf(-ms));
    float c = log1pf(expf(-fabsf(ms)));          // shared softplus tail
    float sp_pos = fmaxf(ms, 0.0f) + c;          // softplus(ms)
    float sp_neg = fmaxf(-ms, 0.0f) + c;         // softplus(-ms)
    float ent = fmaf(p, sp_neg, (1.0f - p) * sp_pos);
    float s;
    if (u < p) { s = 1.0f; atomicAdd(&g_cnt[i * LL + j], 1); } else s = 0.0f;
    out[OFF_MS + f] = ms;
    out[OFF_S + f]  = s;
    out[OFF_E + f]  = ent;
    float lsm = sp_pos - ms * s;
    return make_float2(ent, lsm);
}

// ---------------------------------------------------------------------------
// Pairwise core (EXACT R8 version).
// grid (8, 4, 16): x = j-tile(16), y = i-tile(32), z = batch; 256 threads
// (ty = i 0..31, tx = j 0..7; each thread does j and j+8). Full D=256 smem.
// ---------------------------------------------------------------------------
#define PW_STR 260

__global__ __launch_bounds__(256, 4)
void pairwise_kernel(const float* __restrict__ Uv,
                     const float* __restrict__ biasp,
                     float* __restrict__ out) {
    __shared__ __align__(16) float sl[32 * PW_STR];
    __shared__ __align__(16) float sr[16 * PW_STR];
    __shared__ __align__(16) float su[256];
    __shared__ float rshare[2][8];
    const int tid = threadIdx.x;
    const int tx = tid & 7, ty = tid >> 3;        // j, i within tile
    const int b = blockIdx.z;
    const int ibase = blockIdx.y * 32, jbase = blockIdx.x * 16;

    su[tid] = Uv[tid];
    // load 32 l-rows + 16 r-rows, each 256 floats (64 float4), coalesced
    for (int idx = tid; idx < 48 * 64; idx += 256) {
        int r = idx >> 6, c = (idx & 63) * 4;
        if (r < 32) {
            *(float4*)&sl[r * PW_STR + c] =
                *(const float4*)&g_el[(b * 128 + ibase + r) * 256 + c];
        } else {
            *(float4*)&sr[(r - 32) * PW_STR + c] =
                *(const float4*)&g_er[(b * 128 + jbase + (r - 32)) * 256 + c];
        }
    }
    __syncthreads();

    const float* pl  = sl + ty * PW_STR;
    const float* pr0 = sr + tx * PW_STR;
    const float* pr1 = sr + (tx + 8) * PW_STR;
    float a0 = 0.0f, a1 = 0.0f;
#pragma unroll 4
    for (int d = 0; d < 256; d += 4) {
        float4 L  = *(const float4*)(pl + d);
        float4 R0 = *(const float4*)(pr0 + d);
        float4 R1 = *(const float4*)(pr1 + d);
        float4 UD = *(const float4*)(su + d);
        a0 = fmaf(UD.x, rcpf(fmaf(L.x, R0.x, 1.0f)) - 0.5f, a0);
        a1 = fmaf(UD.x, rcpf(fmaf(L.x, R1.x, 1.0f)) - 0.5f, a1);
        a0 = fmaf(UD.y, rcpf(fmaf(L.y, R0.y, 1.0f)) - 0.5f, a0);
        a1 = fmaf(UD.y, rcpf(fmaf(L.y, R1.y, 1.0f)) - 0.5f, a1);
        a0 = fmaf(UD.z, rcpf(fmaf(L.z, R0.z, 1.0f)) - 0.5f, a0);
        a1 = fmaf(UD.z, rcpf(fmaf(L.z, R1.z, 1.0f)) - 0.5f, a1);
        a0 = fmaf(UD.w, rcpf(fmaf(L.w, R0.w, 1.0f)) - 0.5f, a0);
        a1 = fmaf(UD.w, rcpf(fmaf(L.w, R1.w, 1.0f)) - 0.5f, a1);
    }

    const float bias = __ldg(biasp);
    float2 e0 = epi_one(b, ibase + ty, jbase + tx,     fmaf(-2.0f, a0, bias), out);
    float2 e1 = epi_one(b, ibase + ty, jbase + tx + 8, fmaf(-2.0f, a1, bias), out);

    // block reduce (shfl tree + 8-warp combine), deterministic
    float ent = e0.x + e1.x, lsm = e0.y + e1.y;
#pragma unroll
    for (int o = 16; o > 0; o >>= 1) {
        ent += __shfl_xor_sync(0xffffffffu, ent, o);
        lsm += __shfl_xor_sync(0xffffffffu, lsm, o);
    }
    const int wid = tid >> 5;
    if ((tid & 31) == 0) { rshare[0][wid] = ent; rshare[1][wid] = lsm; }
    __syncthreads();
    if (tid == 0) {
        float se = 0.0f, sm = 0.0f;
#pragma unroll
        for (int w = 0; w < 8; w++) { se += rshare[0][w]; sm += rshare[1][w]; }
        const int bid = (b * 4 + blockIdx.y) * 8 + blockIdx.x; // 0..511
        g_ent_part[bid] = se;
        g_lsm_part[bid] = sm;
    }
}

// ---------------------------------------------------------------------------
// Tail (shrunk): ONE block x 1024 threads.
//  - graph_batch: 4096 int4 -> float4 conversions + reset (4 per thread)
//  - entropy_regularization: threads 0-15 (32 partials each, fixed order)
//  - log_softmax: threads 32-63 (one warp over 512 partials)
// ---------------------------------------------------------------------------
__global__ __launch_bounds__(1024, 1)
void tail_kernel(float* __restrict__ out) {
    const int t = threadIdx.x;
    // graph_batch, vectorized: 16384 ints = 4096 int4
#pragma unroll
    for (int q = 0; q < 4; q++) {
        int idx = q * 1024 + t;                 // 0..4095
        int4 c = ((const int4*)g_cnt)[idx];
        float4 o;
        o.x = (float)c.x * 0.0625f;
        o.y = (float)c.y * 0.0625f;
        o.z = (float)c.z * 0.0625f;
        o.w = (float)c.w * 0.0625f;
        ((float4*)(out + OFF_GB))[idx] = o;
        ((int4*)g_cnt)[idx] = make_int4(0, 0, 0, 0);
    }
    if (t < 16) {   // entropy_reg: 32 tile-partials per batch, fixed order
        float s = 0.0f;
#pragma unroll
        for (int k = 0; k < 32; k++) s += g_ent_part[t * 32 + k];
        out[OFF_ER + t] = s * (1.0f / 16384.0f);
    }
    if (t >= 32 && t < 64) {   // log_softmax: 512 partials
        int lane = t - 32;
        float s = 0.0f;
#pragma unroll
        for (int k = 0; k < 16; k++) s += g_lsm_part[lane * 16 + k];
#pragma unroll
        for (int o = 16; o > 0; o >>= 1)
            s += __shfl_xor_sync(0xffffffffu, s, o);
        if (lane == 0) out[OFF_LSM] = s * (1.0f / (float)NEL);
    }
}

// ---------------------------------------------------------------------------
extern "C" void kernel_launch(void* const* d_in, const int* in_sizes, int n_in,
                              void* d_out, int out_size) {
    (void)in_sizes; (void)n_in; (void)out_size;
    const float* enc  = (const float*)d_in[0]; // (16,128,256)
    const float* W_l  = (const float*)d_in[1]; // (256,256)
    const float* W_r  = (const float*)d_in[2]; // (256,256)
    const float* U    = (const float*)d_in[3]; // (256,)
    const float* bias = (const float*)d_in[4]; // (1,)
    float* out = (float*)d_out;

    gemm_exp_kernel<<<dim3(4, 32, 2), 128>>>(enc, W_l, W_r);
    pairwise_kernel<<<dim3(8, 4, 16), 256>>>(U, bias, out);
    tail_kernel<<<1, 1024>>>(out);
}

// round 17
// speedup vs baseline: 1.7649x; 1.0006x over previous
#include <cuda_runtime.h>
#include <stdint.h>
#include <math.h>

// Sizes (fixed for this problem)
#define BB 16
#define LL 128
#define HH 256
#define DD 256
#define BL (BB*LL)              // 2048
#define NEL (BB*LL*LL)          // 262144
#define OFF_MS 0
#define OFF_S  NEL              // 262144
#define OFF_E  (2*NEL)          // 524288
#define OFF_GB (3*NEL)          // 786432
#define OFF_LSM (3*NEL + LL*LL) // 802816
#define OFF_ER (OFF_LSM + 1)    // 802817

// Scratch (no cudaMalloc allowed). g_el/g_er hold exp(2*dot).
__device__ float g_el[BL*DD];
__device__ float g_er[BL*DD];
__device__ float g_ent_part[512];
__device__ float g_lsm_part[512];
__device__ int   g_cnt[LL*LL];   // zero at load; tail kernel resets each call

#define TWO_LOG2E 2.8853900817779268f   // 2*log2(e)

__device__ __forceinline__ float ex2f(float x) {
    float e; asm("ex2.approx.f32 %0, %1;" : "=f"(e) : "f"(x)); return e;
}
__device__ __forceinline__ float rcpf(float x) {
    float r; asm("rcp.approx.f32 %0, %1;" : "=f"(r) : "f"(x)); return r;
}

// ---------------------------------------------------------------------------
// GEMM: C = exp(2 * (A(2048x256) @ W(256x256))), fp32.  (R8 body)
// 64x64 tile, 128 threads, 8x4 microtile, k-chunk 16, register prefetch.
// As[m][k] stride 20 (LDS.128 a-frags along k), Bs[k][n] stride 68
// (LDS.128 b-frags along n). grid (4, 32, 2) = 256 blocks.
// ONLY change vs R16: __launch_bounds__(128, 4) -> all 256 blocks resident
// in one wave; 4 warps/SMSP on doubled-up SMs hide the LDS latency chains.
// ---------------------------------------------------------------------------
#define AS_STR 20
#define BS_STR 68

__global__ __launch_bounds__(128, 4)
void gemm_exp_kernel(const float* __restrict__ A,
                     const float* __restrict__ Wl,
                     const float* __restrict__ Wr) {
    const float* W = blockIdx.z ? Wr : Wl;
    float* C = blockIdx.z ? g_er : g_el;
    __shared__ __align__(16) float As[64 * AS_STR];
    __shared__ __align__(16) float Bs[16 * BS_STR];
    const int tid = threadIdx.x;
    const int tx = tid & 15, ty = tid >> 4;       // tx: n (0..15), ty: m (0..7)
    const int m0 = blockIdx.y * 64, n0 = blockIdx.x * 64;

    // global load mapping
    const int arow = tid >> 2, acol = (tid & 3) * 4;   // A: 64 rows x 16 k
    const int brow = tid >> 3, bcol = (tid & 7) * 8;   // W: 16 rows x 64 n
    const float* Ap = A + (m0 + arow) * 256 + acol;
    const float* Wp = W + brow * 256 + n0 + bcol;

    float4 ra0 = *(const float4*)(Ap);
    float4 ra1 = *(const float4*)(Ap + 32 * 256);
    float4 rb0 = *(const float4*)(Wp);
    float4 rb1 = *(const float4*)(Wp + 4);

    float acc[8][4];
#pragma unroll
    for (int u = 0; u < 8; u++)
#pragma unroll
        for (int v = 0; v < 4; v++) acc[u][v] = 0.0f;

    for (int s = 0; s < 16; s++) {
        *(float4*)&As[arow * AS_STR + acol]        = ra0;
        *(float4*)&As[(arow + 32) * AS_STR + acol] = ra1;
        *(float4*)&Bs[brow * BS_STR + bcol]        = rb0;
        *(float4*)&Bs[brow * BS_STR + bcol + 4]    = rb1;
        __syncthreads();
        if (s < 15) {
            ra0 = *(const float4*)(Ap + (s + 1) * 16);
            ra1 = *(const float4*)(Ap + (s + 1) * 16 + 32 * 256);
            rb0 = *(const float4*)(Wp + (s + 1) * 16 * 256);
            rb1 = *(const float4*)(Wp + (s + 1) * 16 * 256 + 4);
        }
#pragma unroll
        for (int kq = 0; kq < 16; kq += 4) {
            // a-fragments: 8 float4 loads, transposed into scalar regs [kk][mi]
            float a_s[4][8];
#pragma unroll
            for (int i = 0; i < 4; i++) {
                float4 lo = *(const float4*)&As[(4 * ty + i) * AS_STR + kq];
                float4 hi = *(const float4*)&As[(32 + 4 * ty + i) * AS_STR + kq];
                a_s[0][i] = lo.x; a_s[1][i] = lo.y; a_s[2][i] = lo.z; a_s[3][i] = lo.w;
                a_s[0][i + 4] = hi.x; a_s[1][i + 4] = hi.y;
                a_s[2][i + 4] = hi.z; a_s[3][i + 4] = hi.w;
            }
            // b-fragments: 4 float4 loads [kk]
            float4 b4[4];
#pragma unroll
            for (int kk = 0; kk < 4; kk++)
                b4[kk] = *(const float4*)&Bs[(kq + kk) * BS_STR + 4 * tx];
#pragma unroll
            for (int kk = 0; kk < 4; kk++) {
#pragma unroll
                for (int mi = 0; mi < 8; mi++) {
                    float av = a_s[kk][mi];
                    acc[mi][0] = fmaf(av, b4[kk].x, acc[mi][0]);
                    acc[mi][1] = fmaf(av, b4[kk].y, acc[mi][1]);
                    acc[mi][2] = fmaf(av, b4[kk].z, acc[mi][2]);
                    acc[mi][3] = fmaf(av, b4[kk].w, acc[mi][3]);
                }
            }
        }
        __syncthreads();
    }
#pragma unroll
    for (int mi = 0; mi < 8; mi++) {
        int m = m0 + ((mi < 4) ? (4 * ty + mi) : (32 + 4 * ty + (mi - 4)));
        float4 o;
        o.x = ex2f(acc[mi][0] * TWO_LOG2E);
        o.y = ex2f(acc[mi][1] * TWO_LOG2E);
        o.z = ex2f(acc[mi][2] * TWO_LOG2E);
        o.w = ex2f(acc[mi][3] * TWO_LOG2E);
        *(float4*)&C[m * 256 + n0 + 4 * tx] = o;
    }
}

// ---------------------------------------------------------------------------
// Threefry-2x32, key = (0,1) [jax.random.key(1)], partitionable bits.
// ---------------------------------------------------------------------------
__device__ __forceinline__ uint32_t rotl32(uint32_t v, int r) {
    return __funnelshift_l(v, v, r);
}
__device__ __forceinline__ uint32_t threefry_bits(uint32_t idx) {
    const uint32_t K0 = 0u, K1 = 1u, K2 = 0x1BD11BDBu;
    uint32_t x0 = K0;
    uint32_t x1 = idx + K1;
#define TF_ROUND(r) { x0 += x1; x1 = rotl32(x1, (r)); x1 ^= x0; }
    TF_ROUND(13) TF_ROUND(15) TF_ROUND(26) TF_ROUND(6)
    x0 += K1; x1 += K2 + 1u;
    TF_ROUND(17) TF_ROUND(29) TF_ROUND(16) TF_ROUND(24)
    x0 += K2; x1 += K0 + 2u;
    TF_ROUND(13) TF_ROUND(15) TF_ROUND(26) TF_ROUND(6)
    x0 += K0; x1 += K1 + 3u;
    TF_ROUND(17) TF_ROUND(29) TF_ROUND(16) TF_ROUND(24)
    x0 += K1; x1 += K2 + 4u;
    TF_ROUND(13) TF_ROUND(15) TF_ROUND(26) TF_ROUND(6)
    x0 += K2; x1 += K0 + 5u;
#undef TF_ROUND
    return x0 ^ x1;
}

// Epilogue for one (b,i,j): writes ms/sample/entropy, counts sample into
// g_cnt (integer atomic -> deterministic), returns (entropy, lsm_term).
__device__ __forceinline__ float2 epi_one(int b, int i, int j, float logit,
                                          float* __restrict__ out) {
    float ms = (i == j) ? (logit - 1e8f) : logit;
    uint32_t f = ((uint32_t)b << 14) | ((uint32_t)i << 7) | (uint32_t)j;
    uint32_t bits = threefry_bits(f);
    float u = __uint_as_float((bits >> 9) | 0x3f800000u) - 1.0f;
    float p = 1.0f / (1.0f + expf(-ms));
    float c = log1pf(expf(-fabsf(ms)));          // shared softplus tail
    float sp_pos = fmaxf(ms, 0.0f) + c;          // softplus(ms)
    float sp_neg = fmaxf(-ms, 0.0f) + c;         // softplus(-ms)
    float ent = fmaf(p, sp_neg, (1.0f - p) * sp_pos);
    float s;
    if (u < p) { s = 1.0f; atomicAdd(&g_cnt[i * LL + j], 1); } else s = 0.0f;
    out[OFF_MS + f] = ms;
    out[OFF_S + f]  = s;
    out[OFF_E + f]  = ent;
    float lsm = sp_pos - ms * s;
    return make_float2(ent, lsm);
}

// ---------------------------------------------------------------------------
// Pairwise core (EXACT R8 version — do not touch).
// grid (8, 4, 16): x = j-tile(16), y = i-tile(32), z = batch; 256 threads
// (ty = i 0..31, tx = j 0..7; each thread does j and j+8). Full D=256 smem.
// ---------------------------------------------------------------------------
#define PW_STR 260

__global__ __launch_bounds__(256, 4)
void pairwise_kernel(const float* __restrict__ Uv,
                     const float* __restrict__ biasp,
                     float* __restrict__ out) {
    __shared__ __align__(16) float sl[32 * PW_STR];
    __shared__ __align__(16) float sr[16 * PW_STR];
    __shared__ __align__(16) float su[256];
    __shared__ float rshare[2][8];
    const int tid = threadIdx.x;
    const int tx = tid & 7, ty = tid >> 3;        // j, i within tile
    const int b = blockIdx.z;
    const int ibase = blockIdx.y * 32, jbase = blockIdx.x * 16;

    su[tid] = Uv[tid];
    // load 32 l-rows + 16 r-rows, each 256 floats (64 float4), coalesced
    for (int idx = tid; idx < 48 * 64; idx += 256) {
        int r = idx >> 6, c = (idx & 63) * 4;
        if (r < 32) {
            *(float4*)&sl[r * PW_STR + c] =
                *(const float4*)&g_el[(b * 128 + ibase + r) * 256 + c];
        } else {
            *(float4*)&sr[(r - 32) * PW_STR + c] =
                *(const float4*)&g_er[(b * 128 + jbase + (r - 32)) * 256 + c];
        }
    }
    __syncthreads();

    const float* pl  = sl + ty * PW_STR;
    const float* pr0 = sr + tx * PW_STR;
    const float* pr1 = sr + (tx + 8) * PW_STR;
    float a0 = 0.0f, a1 = 0.0f;
#pragma unroll 4
    for (int d = 0; d < 256; d += 4) {
        float4 L  = *(const float4*)(pl + d);
        float4 R0 = *(const float4*)(pr0 + d);
        float4 R1 = *(const float4*)(pr1 + d);
        float4 UD = *(const float4*)(su + d);
        a0 = fmaf(UD.x, rcpf(fmaf(L.x, R0.x, 1.0f)) - 0.5f, a0);
        a1 = fmaf(UD.x, rcpf(fmaf(L.x, R1.x, 1.0f)) - 0.5f, a1);
        a0 = fmaf(UD.y, rcpf(fmaf(L.y, R0.y, 1.0f)) - 0.5f, a0);
        a1 = fmaf(UD.y, rcpf(fmaf(L.y, R1.y, 1.0f)) - 0.5f, a1);
        a0 = fmaf(UD.z, rcpf(fmaf(L.z, R0.z, 1.0f)) - 0.5f, a0);
        a1 = fmaf(UD.z, rcpf(fmaf(L.z, R1.z, 1.0f)) - 0.5f, a1);
        a0 = fmaf(UD.w, rcpf(fmaf(L.w, R0.w, 1.0f)) - 0.5f, a0);
        a1 = fmaf(UD.w, rcpf(fmaf(L.w, R1.w, 1.0f)) - 0.5f, a1);
    }

    const float bias = __ldg(biasp);
    float2 e0 = epi_one(b, ibase + ty, jbase + tx,     fmaf(-2.0f, a0, bias), out);
    float2 e1 = epi_one(b, ibase + ty, jbase + tx + 8, fmaf(-2.0f, a1, bias), out);

    // block reduce (shfl tree + 8-warp combine), deterministic
    float ent = e0.x + e1.x, lsm = e0.y + e1.y;
#pragma unroll
    for (int o = 16; o > 0; o >>= 1) {
        ent += __shfl_xor_sync(0xffffffffu, ent, o);
        lsm += __shfl_xor_sync(0xffffffffu, lsm, o);
    }
    const int wid = tid >> 5;
    if ((tid & 31) == 0) { rshare[0][wid] = ent; rshare[1][wid] = lsm; }
    __syncthreads();
    if (tid == 0) {
        float se = 0.0f, sm = 0.0f;
#pragma unroll
        for (int w = 0; w < 8; w++) { se += rshare[0][w]; sm += rshare[1][w]; }
        const int bid = (b * 4 + blockIdx.y) * 8 + blockIdx.x; // 0..511
        g_ent_part[bid] = se;
        g_lsm_part[bid] = sm;
    }
}

// ---------------------------------------------------------------------------
// Tail: ONE block x 1024 threads.
//  - graph_batch: 4096 int4 -> float4 conversions + reset (4 per thread)
//  - entropy_regularization: threads 0-15 (32 partials each, fixed order)
//  - log_softmax: threads 32-63 (one warp over 512 partials)
// ---------------------------------------------------------------------------
__global__ __launch_bounds__(1024, 1)
void tail_kernel(float* __restrict__ out) {
    const int t = threadIdx.x;
    // graph_batch, vectorized: 16384 ints = 4096 int4
#pragma unroll
    for (int q = 0; q < 4; q++) {
        int idx = q * 1024 + t;                 // 0..4095
        int4 c = ((const int4*)g_cnt)[idx];
        float4 o;
        o.x = (float)c.x * 0.0625f;
        o.y = (float)c.y * 0.0625f;
        o.z = (float)c.z * 0.0625f;
        o.w = (float)c.w * 0.0625f;
        ((float4*)(out + OFF_GB))[idx] = o;
        ((int4*)g_cnt)[idx] = make_int4(0, 0, 0, 0);
    }
    if (t < 16) {   // entropy_reg: 32 tile-partials per batch, fixed order
        float s = 0.0f;
#pragma unroll
        for (int k = 0; k < 32; k++) s += g_ent_part[t * 32 + k];
        out[OFF_ER + t] = s * (1.0f / 16384.0f);
    }
    if (t >= 32 && t < 64) {   // log_softmax: 512 partials
        int lane = t - 32;
        float s = 0.0f;
#pragma unroll
        for (int k = 0; k < 16; k++) s += g_lsm_part[lane * 16 + k];
#pragma unroll
        for (int o = 16; o > 0; o >>= 1)
            s += __shfl_xor_sync(0xffffffffu, s, o);
        if (lane == 0) out[OFF_LSM] = s * (1.0f / (float)NEL);
    }
}

// ---------------------------------------------------------------------------
extern "C" void kernel_launch(void* const* d_in, const int* in_sizes, int n_in,
                              void* d_out, int out_size) {
    (void)in_sizes; (void)n_in; (void)out_size;
    const float* enc  = (const float*)d_in[0]; // (16,128,256)
    const float* W_l  = (const float*)d_in[1]; // (256,256)
    const float* W_r  = (const float*)d_in[2]; // (256,256)
    const float* U    = (const float*)d_in[3]; // (256,)
    const float* bias = (const float*)d_in[4]; // (1,)
    float* out = (float*)d_out;

    gemm_exp_kernel<<<dim3(4, 32, 2), 128>>>(enc, W_l, W_r);
    pairwise_kernel<<<dim3(8, 4, 16), 256>>>(U, bias, out);
    tail_kernel<<<1, 1024>>>(out);
}